// round 9
// baseline (speedup 1.0000x reference)
#include <cuda_runtime.h>
#include <cuda_bf16.h>
#include <mma.h>
#include <cstdint>
#include <cstdio>

using namespace nvcuda;

constexpr int N_TOK = 4096;
constexpr int DIM = 256;
constexpr int NUM_LAYERS = 20;
constexpr int NUM_HEADS = 200;
constexpr int ND = N_TOK * DIM;

// ---------------- static device scratch (no cudaMalloc allowed) ----------------
__device__ __nv_bfloat16 g_xbf[ND];                                // x in bf16
__device__ uint8_t       g_QKV[(size_t)NUM_HEADS * 3 * ND];        // fp8 e4m3: [head][q|k|vT]
__device__ __nv_bfloat16 g_O[(size_t)NUM_HEADS * ND];              // per-head attention out (bf16)
__device__ float         g_h[2 * ND];                              // MLP ping-pong

__device__ __forceinline__ float tanh_apx(float x) {
    float y; asm("tanh.approx.f32 %0, %1;" : "=f"(y) : "f"(x)); return y;
}
// p = e^u, u in [-0.5, 0.5] (deg-4 Taylor, rel err ~1.6e-4, common-mode cancels in softmax)
__device__ __forceinline__ float exp_poly(float u) {
    float p = fmaf(u, 0.041666667f, 0.16666667f);
    p = fmaf(u, p, 0.5f);
    p = fmaf(u, p, 1.0f);
    p = fmaf(u, p, 1.0f);
    return p;
}
__device__ __forceinline__ float softp(float s) {
    return exp_poly(0.5f * tanh_apx(0.03125f * s));
}
__device__ __forceinline__ uint16_t pack_e4m3(float hi, float lo) {
    uint16_t r; asm("cvt.rn.satfinite.e4m3x2.f32 %0, %1, %2;" : "=h"(r) : "f"(hi), "f"(lo));
    return r;
}
__device__ __forceinline__ uint32_t pack_e4m3x4(float f0, float f1, float f2, float f3) {
    uint16_t a = pack_e4m3(f1, f0);
    uint16_t b = pack_e4m3(f3, f2);
    return (uint32_t)a | ((uint32_t)b << 16);
}
__device__ __forceinline__ uint32_t smem_to_u32(const void* p) {
    uint32_t a;
    asm("{ .reg .u64 t; cvta.to.shared.u64 t, %1; cvt.u32.u64 %0, t; }" : "=r"(a) : "l"(p));
    return a;
}

// ---- baseline-PTX building blocks ----
__device__ __forceinline__ void mma_fp8(float* c, const uint32_t* a, uint32_t b0, uint32_t b1) {
    asm volatile(
        "mma.sync.aligned.m16n8k32.row.col.f32.e4m3.e4m3.f32 "
        "{%0,%1,%2,%3}, {%4,%5,%6,%7}, {%8,%9}, {%0,%1,%2,%3};"
        : "+f"(c[0]), "+f"(c[1]), "+f"(c[2]), "+f"(c[3])
        : "r"(a[0]), "r"(a[1]), "r"(a[2]), "r"(a[3]), "r"(b0), "r"(b1));
}
__device__ __forceinline__ void ldsm4(uint32_t* r, uint32_t addr) {
    asm volatile("ldmatrix.sync.aligned.m8n8.x4.shared.b16 {%0,%1,%2,%3}, [%4];"
                 : "=r"(r[0]), "=r"(r[1]), "=r"(r[2]), "=r"(r[3]) : "r"(addr));
}
__device__ __forceinline__ void st16s(uint32_t addr, uint16_t v) {
    asm volatile("st.shared.u16 [%0], %1;" :: "r"(addr), "h"(v));
}
#define CP_ASYNC16(dst, src) \
    asm volatile("cp.async.cg.shared.global [%0], [%1], 16;" :: "r"(dst), "l"(src))
#define CP_COMMIT() asm volatile("cp.async.commit_group;" ::: "memory")
#define CP_WAIT1() asm volatile("cp.async.wait_group 1;" ::: "memory")
#define CP_WAIT0() asm volatile("cp.async.wait_group 0;" ::: "memory")

// ---------------- prep: x fp32 -> bf16 ----------------
__global__ void prep_kernel(const float* __restrict__ x) {
    int i = blockIdx.x * blockDim.x + threadIdx.x;
    g_xbf[i] = __float2bfloat16(x[i]);
}

// ---------------- QKV projection: C = x @ W^T + b  -> fp8 e4m3 (V transposed) ----------------
constexpr int PROJ_SMEM = 135168;

__global__ __launch_bounds__(256) void proj_kernel(
    const float* __restrict__ Wq, const float* __restrict__ bq,
    const float* __restrict__ Wk, const float* __restrict__ bk,
    const float* __restrict__ Wv, const float* __restrict__ bv) {
    extern __shared__ char sm[];
    __nv_bfloat16* Xs = (__nv_bfloat16*)sm;             // [128][264]
    __nv_bfloat16* Ws = (__nv_bfloat16*)(sm + 67584);   // [128][264]
    float*         Cs = (float*)sm;                     // [128][132] (reuse)
    __shared__ float bias_s[128];

    const int tid = threadIdx.x;
    const int mat = blockIdx.z;
    const int head = mat / 3, w = mat % 3;
    const float* W    = (w == 0 ? Wq : (w == 1 ? Wk : Wv)) + (size_t)head * DIM * DIM;
    const float* bias = (w == 0 ? bq : (w == 1 ? bk : bv)) + head * DIM;
    const int n0 = blockIdx.x * 128;
    const int j0 = blockIdx.y * 128;

    if (tid < 128) bias_s[tid] = bias[j0 + tid];

    for (int t = tid; t < 4096; t += 256) {
        int r = t >> 5, kc = (t & 31) << 3;
        *(uint4*)&Xs[r * 264 + kc] = *(const uint4*)&g_xbf[(size_t)(n0 + r) * DIM + kc];
    }
    for (int t = tid; t < 8192; t += 256) {
        int j = t >> 6, kc = (t & 63) << 2;
        float4 v = *(const float4*)&W[(size_t)(j0 + j) * DIM + kc];
        *(__nv_bfloat162*)&Ws[j * 264 + kc]     = __floats2bfloat162_rn(v.x, v.y);
        *(__nv_bfloat162*)&Ws[j * 264 + kc + 2] = __floats2bfloat162_rn(v.z, v.w);
    }
    __syncthreads();

    const int wid = tid >> 5;
    const int wr = (wid & 3) * 32;
    const int wc = (wid >> 2) * 64;
    wmma::fragment<wmma::accumulator, 16, 16, 16, float> c[2][4];
#pragma unroll
    for (int i = 0; i < 2; i++)
#pragma unroll
        for (int j = 0; j < 4; j++) wmma::fill_fragment(c[i][j], 0.f);

#pragma unroll
    for (int kk = 0; kk < 16; kk++) {
        wmma::fragment<wmma::matrix_a, 16, 16, 16, __nv_bfloat16, wmma::row_major> a[2];
#pragma unroll
        for (int i = 0; i < 2; i++)
            wmma::load_matrix_sync(a[i], &Xs[(wr + i * 16) * 264 + kk * 16], 264);
        wmma::fragment<wmma::matrix_b, 16, 16, 16, __nv_bfloat16, wmma::col_major> b[4];
#pragma unroll
        for (int j = 0; j < 4; j++)
            wmma::load_matrix_sync(b[j], &Ws[(wc + j * 16) * 264 + kk * 16], 264);
#pragma unroll
        for (int i = 0; i < 2; i++)
#pragma unroll
            for (int j = 0; j < 4; j++)
                wmma::mma_sync(c[i][j], a[i], b[j], c[i][j]);
    }
    __syncthreads();

    if (w == 2) {
        // V: store transposed into Cs -> Cs[j][n] = C[n][j]
#pragma unroll
        for (int i = 0; i < 2; i++)
#pragma unroll
            for (int j = 0; j < 4; j++)
                wmma::store_matrix_sync(&Cs[(size_t)(wc + j * 16) * 132 + (wr + i * 16)],
                                        c[i][j], 132, wmma::mem_col_major);
    } else {
#pragma unroll
        for (int i = 0; i < 2; i++)
#pragma unroll
            for (int j = 0; j < 4; j++)
                wmma::store_matrix_sync(&Cs[(size_t)(wr + i * 16) * 132 + wc + j * 16],
                                        c[i][j], 132, wmma::mem_row_major);
    }
    __syncthreads();

    if (w == 2) {
        // write V^T fp8: [d][tok]
        uint8_t* outT = g_QKV + (size_t)mat * ND;
        for (int t = tid; t < 4096; t += 256) {
            int j = t >> 5, c0 = (t & 31) << 2;
            float4 v = *(float4*)&Cs[j * 132 + c0];
            float bb = bias_s[j];
            uint32_t pk = pack_e4m3x4(v.x + bb, v.y + bb, v.z + bb, v.w + bb);
            *(uint32_t*)(outT + (size_t)(j0 + j) * N_TOK + n0 + c0) = pk;
        }
    } else {
        uint8_t* out = g_QKV + (size_t)mat * ND;
        for (int t = tid; t < 4096; t += 256) {
            int r = t >> 5, c0 = (t & 31) << 2;
            float4 v = *(float4*)&Cs[r * 132 + c0];
            uint32_t pk = pack_e4m3x4(v.x + bias_s[c0], v.y + bias_s[c0 + 1],
                                      v.z + bias_s[c0 + 2], v.w + bias_s[c0 + 3]);
            *(uint32_t*)(out + (size_t)(n0 + r) * DIM + j0 + c0) = pk;
        }
    }
}

// ================= FP8 FA2-style fused flash attention (mma.sync e4m3) =================
// BM=128 q rows/CTA, 8 warps x 16 rows, BN=64 keys/tile, d=256 in fp32 regs.
// S in C-frags -> softmax in regs -> P bounced via per-warp SMEM (fp8 A-frags via ldsm4).
constexpr int Q_OFF  = 0;                 // fp8 [128][272B]  (256B data + 16 pad)
constexpr int K_OFF  = 34816;             // 2 stages x fp8 [64][272B]
constexpr int K_STG  = 17408;
constexpr int VT_OFF = 69632;             // 2 stages x fp8 [256][80B] (V^T: [d][key])
constexpr int VT_STG = 20480;
constexpr int P_OFF  = 110592;            // 8 warps x [16][80B]
constexpr int ATTN_SMEM = 120832;

__global__ __launch_bounds__(256, 1) void attn_kernel() {
    extern __shared__ char sm[];
    const uint32_t sbase = smem_to_u32(sm);
    const int tid = threadIdx.x, wid = tid >> 5, lane = tid & 31;
    const int head = blockIdx.y;
    const int q0 = blockIdx.x * 128;
    const uint8_t* Qg  = g_QKV + (size_t)(head * 3 + 0) * ND + (size_t)q0 * DIM;
    const uint8_t* Kg  = g_QKV + (size_t)(head * 3 + 1) * ND;
    const uint8_t* VTg = g_QKV + (size_t)(head * 3 + 2) * ND;   // [d=256][tok=4096]

    // Q -> smem (row stride 272B)
    for (int t = tid; t < 2048; t += 256) {
        int row = t >> 4, ch = t & 15;
        *(uint4*)(sm + Q_OFF + row * 272 + ch * 16) = *(const uint4*)(Qg + row * 256 + ch * 16);
    }

    // K tile: 64 rows x 256B; V^T tile: 256 rows x 64B. 4 cp.async chunks each per thread.
    auto issueKV = [&](int kt, int stage) {
        uint32_t kd = sbase + K_OFF + stage * K_STG;
        uint32_t vd = sbase + VT_OFF + stage * VT_STG;
        const uint8_t* Ksrc = Kg + (size_t)kt * 64 * DIM;
        const uint8_t* Vsrc = VTg + kt * 64;
#pragma unroll
        for (int i = 0; i < 4; i++) {
            int t = tid + i * 256;
            int krow = t >> 4, kch = t & 15;
            CP_ASYNC16(kd + krow * 272 + kch * 16, Ksrc + krow * 256 + kch * 16);
            int vrow = t >> 2, vch = t & 3;
            CP_ASYNC16(vd + vrow * 80 + vch * 16, Vsrc + (size_t)vrow * N_TOK + vch * 16);
        }
    };
    issueKV(0, 0); CP_COMMIT();
    issueKV(1, 1); CP_COMMIT();

    const int r0 = wid * 16;
    const int r = lane >> 2, q = lane & 3;
    const uint32_t qa = sbase + Q_OFF + (uint32_t)(r0 + (lane & 15)) * 272 + ((lane >> 4) << 4);
    const uint32_t ka = (uint32_t)((lane & 7) + ((lane >> 4) << 3)) * 272 + (((lane >> 3) & 1) << 4);
    const uint32_t va = (uint32_t)((lane & 7) + ((lane >> 4) << 3)) * 80 + (((lane >> 3) & 1) << 4);
    const uint32_t Pw = sbase + P_OFF + wid * 1280;
    const uint32_t pa = Pw + (uint32_t)(lane & 15) * 80 + ((lane >> 4) << 4);

    float o[128];
#pragma unroll
    for (int i = 0; i < 128; i++) o[i] = 0.f;
    float rsum0 = 0.f, rsum1 = 0.f;

    for (int kt = 0; kt < 64; kt++) {
        if (kt < 63) { CP_WAIT1(); } else { CP_WAIT0(); }
        __syncthreads();
        const uint32_t Kst  = sbase + K_OFF + (kt & 1) * K_STG;
        const uint32_t VTst = sbase + VT_OFF + (kt & 1) * VT_STG;

        // ---- S = Q @ K^T (16x64 per warp, k=256 fp8, 8 k-steps of 32) ----
        float s[32];
#pragma unroll
        for (int i = 0; i < 32; i++) s[i] = 0.f;
#pragma unroll
        for (int kk = 0; kk < 8; kk++) {
            uint32_t a[4];
            ldsm4(a, qa + kk * 32);
#pragma unroll
            for (int np = 0; np < 4; np++) {
                uint32_t b[4];
                ldsm4(b, Kst + ka + np * 4352 + kk * 32);
                mma_fp8(&s[np * 8], a, b[0], b[1]);
                mma_fp8(&s[np * 8 + 4], a, b[2], b[3]);
            }
        }
        // ---- p = e^{0.5*tanh(s/32)} (1 MUFU + poly); rowsums; fp8 P -> warp SMEM ----
#pragma unroll
        for (int np = 0; np < 4; np++)
#pragma unroll
            for (int h = 0; h < 2; h++) {
                int b = np * 8 + h * 4;
                float p0 = softp(s[b + 0]), p1 = softp(s[b + 1]);
                float p2 = softp(s[b + 2]), p3 = softp(s[b + 3]);
                rsum0 += p0 + p1; rsum1 += p2 + p3;
                uint32_t col = 8 * (2 * np + h) + 2 * q;
                st16s(Pw + (uint32_t)r * 80 + col, pack_e4m3(p1, p0));
                st16s(Pw + (uint32_t)(r + 8) * 80 + col, pack_e4m3(p3, p2));
            }
        __syncwarp();
        // ---- O += P @ V (16x256 per warp, k=64 fp8, 2 k-steps) ----
#pragma unroll
        for (int kk2 = 0; kk2 < 2; kk2++) {
            uint32_t pA[4];
            ldsm4(pA, pa + kk2 * 32);
#pragma unroll
            for (int np2 = 0; np2 < 16; np2++) {
                uint32_t b[4];
                ldsm4(b, VTst + va + np2 * 1280 + kk2 * 32);
                mma_fp8(&o[np2 * 8], pA, b[0], b[1]);
                mma_fp8(&o[np2 * 8 + 4], pA, b[2], b[3]);
            }
        }
        if (kt < 62) {
            __syncthreads();
            issueKV(kt + 2, kt & 1);
            CP_COMMIT();
        }
    }

    // ---- finalize: complete row sums across the quad, normalize, store bf16 ----
    rsum0 += __shfl_xor_sync(0xffffffffu, rsum0, 1);
    rsum0 += __shfl_xor_sync(0xffffffffu, rsum0, 2);
    rsum1 += __shfl_xor_sync(0xffffffffu, rsum1, 1);
    rsum1 += __shfl_xor_sync(0xffffffffu, rsum1, 2);
    float inv0 = 1.0f / rsum0, inv1 = 1.0f / rsum1;

    const int row = q0 + r0 + r;
    __nv_bfloat16* O0 = g_O + (size_t)head * ND + (size_t)row * DIM;
    __nv_bfloat16* O1 = O0 + 8 * DIM;
#pragma unroll
    for (int np2 = 0; np2 < 16; np2++)
#pragma unroll
        for (int h = 0; h < 2; h++) {
            int idx = np2 * 8 + 4 * h;
            int col = 8 * (2 * np2 + h) + 2 * q;
            *(__nv_bfloat162*)&O0[col] = __floats2bfloat162_rn(o[idx] * inv0, o[idx + 1] * inv0);
            *(__nv_bfloat162*)&O1[col] = __floats2bfloat162_rn(o[idx + 2] * inv1, o[idx + 3] * inv1);
        }
}

// ---------------- mean over heads (deterministic, no atomics) ----------------
__global__ void reduce_kernel(float* __restrict__ out) {
    int i = blockIdx.x * blockDim.x + threadIdx.x;
    const __nv_bfloat16* p = g_O + i;
    float s = 0.f;
#pragma unroll 8
    for (int h = 0; h < NUM_HEADS; h++) s += __bfloat162float(p[(size_t)h * ND]);
    out[i] = s * (1.0f / NUM_HEADS);
}

// ---------------- fp32 GEMM for MLP/final (precision-critical path) ----------------
__global__ __launch_bounds__(256) void gemm_fp32(
    const float* __restrict__ A, const float* __restrict__ B,
    const float* __restrict__ bias, float* __restrict__ C,
    int transB, int mode) {
    __shared__ float As[16][68];
    __shared__ float Bs[16][68];
    const int tid = threadIdx.x;
    const int n0 = blockIdx.x * 64;
    const int j0 = blockIdx.y * 64;
    const int r0 = (tid >> 4) * 4;
    const int c0 = (tid & 15) * 4;
    float acc[4][4];
#pragma unroll
    for (int i = 0; i < 4; i++)
#pragma unroll
        for (int j = 0; j < 4; j++) acc[i][j] = 0.f;

    for (int ko = 0; ko < DIM; ko += 16) {
        __syncthreads();
        {
            int k = tid & 15, n = tid >> 4;
#pragma unroll
            for (int p = 0; p < 4; p++)
                As[k][n + 16 * p] = A[(size_t)(n0 + n + 16 * p) * DIM + ko + k];
            if (transB) {
#pragma unroll
                for (int p = 0; p < 4; p++)
                    Bs[k][n + 16 * p] = B[(size_t)(j0 + n + 16 * p) * DIM + ko + k];
            } else {
                int j = tid & 63, kq = tid >> 6;
#pragma unroll
                for (int p = 0; p < 4; p++)
                    Bs[kq + 4 * p][j] = B[(size_t)(ko + kq + 4 * p) * DIM + j0 + j];
            }
        }
        __syncthreads();
#pragma unroll
        for (int kk = 0; kk < 16; kk++) {
            float4 a = *(const float4*)&As[kk][r0];
            float4 b = *(const float4*)&Bs[kk][c0];
            float av[4] = {a.x, a.y, a.z, a.w};
            float bv[4] = {b.x, b.y, b.z, b.w};
#pragma unroll
            for (int i = 0; i < 4; i++)
#pragma unroll
                for (int j = 0; j < 4; j++) acc[i][j] += av[i] * bv[j];
        }
    }
#pragma unroll
    for (int i = 0; i < 4; i++) {
        int n = n0 + r0 + i;
        float4 v;
        float* vp = &v.x;
#pragma unroll
        for (int j = 0; j < 4; j++) {
            int cidx = j0 + c0 + j;
            float t = acc[i][j];
            if (mode == 0) { t += bias[cidx]; t = t > 0.f ? t : 0.f; }
            else           { t = 1.f / (1.f + expf(-t)) + bias[cidx]; }
            vp[j] = t;
        }
        *(float4*)&C[(size_t)n * DIM + j0 + c0] = v;
    }
}

// ---------------- launch ----------------
extern "C" void kernel_launch(void* const* d_in, const int* in_sizes, int n_in,
                              void* d_out, int out_size) {
    const float* x  = (const float*)d_in[0];
    const float* Wq = (const float*)d_in[1];
    const float* bq = (const float*)d_in[2];
    const float* Wk = (const float*)d_in[3];
    const float* bk = (const float*)d_in[4];
    const float* Wv = (const float*)d_in[5];
    const float* bv = (const float*)d_in[6];
    const float* Wl = (const float*)d_in[7];
    const float* bl = (const float*)d_in[8];
    const float* fw = (const float*)d_in[9];
    const float* fb = (const float*)d_in[10];

    cudaFuncSetAttribute(proj_kernel, cudaFuncAttributeMaxDynamicSharedMemorySize, PROJ_SMEM);
    cudaFuncSetAttribute(attn_kernel, cudaFuncAttributeMaxDynamicSharedMemorySize, ATTN_SMEM);

    float* hbuf = nullptr;
    cudaGetSymbolAddress((void**)&hbuf, g_h);

    prep_kernel<<<ND / 256, 256>>>(x);
    proj_kernel<<<dim3(N_TOK / 128, 2, 3 * NUM_HEADS), 256, PROJ_SMEM>>>(Wq, bq, Wk, bk, Wv, bv);
    attn_kernel<<<dim3(N_TOK / 128, NUM_HEADS), 256, ATTN_SMEM>>>();
    reduce_kernel<<<ND / 256, 256>>>(hbuf);

    for (int l = 0; l < NUM_LAYERS; l++) {
        gemm_fp32<<<dim3(N_TOK / 64, DIM / 64), 256>>>(
            hbuf + (size_t)(l & 1) * ND, Wl + (size_t)l * DIM * DIM, bl + l * DIM,
            hbuf + (size_t)((l + 1) & 1) * ND, 1, 0);
    }
    gemm_fp32<<<dim3(N_TOK / 64, DIM / 64), 256>>>(hbuf, fw, fb, (float*)d_out, 0, 1);
}

// round 11
// speedup vs baseline: 1.2508x; 1.2508x over previous
#include <cuda_runtime.h>
#include <cuda_bf16.h>
#include <cstdint>
#include <cstdio>

constexpr int N_TOK = 4096;
constexpr int DIM = 256;
constexpr int NUM_LAYERS = 20;
constexpr int NUM_HEADS = 200;
constexpr int ND = N_TOK * DIM;
constexpr int WSZ = DIM * DIM;   // 65536

// ---------------- static device scratch (no cudaMalloc allowed) ----------------
__device__ __nv_bfloat16 g_xbf[ND];                                // x in bf16
__device__ __nv_bfloat16 g_Wb[(size_t)(3 * NUM_HEADS + NUM_LAYERS + 1) * WSZ];  // all weights bf16
__device__ __nv_bfloat16 g_QKV[(size_t)NUM_HEADS * 3 * ND];        // [head][q|k|v][n][d]
__device__ __nv_bfloat16 g_O[(size_t)NUM_HEADS * ND];              // per-head attention out
__device__ __nv_bfloat16 g_hb[2 * ND];                             // MLP ping-pong (bf16)

__device__ __forceinline__ float tanh_apx(float x) {
    float y; asm("tanh.approx.f32 %0, %1;" : "=f"(y) : "f"(x)); return y;
}
// p = e^u, u in [-0.5,0.5]; deg-4 Taylor (rel err ~1.6e-4, common-mode cancels in softmax)
__device__ __forceinline__ float exp_poly(float u) {
    float p = fmaf(u, 0.041666667f, 0.16666667f);
    p = fmaf(u, p, 0.5f);
    p = fmaf(u, p, 1.0f);
    p = fmaf(u, p, 1.0f);
    return p;
}
__device__ __forceinline__ float softp(float s) {
    return exp_poly(0.5f * tanh_apx(0.03125f * s));
}
__device__ __forceinline__ uint32_t smem_to_u32(const void* p) {
    uint32_t a;
    asm("{ .reg .u64 t; cvta.to.shared.u64 t, %1; cvt.u32.u64 %0, t; }" : "=r"(a) : "l"(p));
    return a;
}

// ---- baseline-PTX building blocks ----
__device__ __forceinline__ void mma16816(float* c, const uint32_t* a, uint32_t b0, uint32_t b1) {
    asm volatile(
        "mma.sync.aligned.m16n8k16.row.col.f32.bf16.bf16.f32 "
        "{%0,%1,%2,%3}, {%4,%5,%6,%7}, {%8,%9}, {%0,%1,%2,%3};"
        : "+f"(c[0]), "+f"(c[1]), "+f"(c[2]), "+f"(c[3])
        : "r"(a[0]), "r"(a[1]), "r"(a[2]), "r"(a[3]), "r"(b0), "r"(b1));
}
__device__ __forceinline__ void ldsm4(uint32_t* r, uint32_t addr) {
    asm volatile("ldmatrix.sync.aligned.m8n8.x4.shared.b16 {%0,%1,%2,%3}, [%4];"
                 : "=r"(r[0]), "=r"(r[1]), "=r"(r[2]), "=r"(r[3]) : "r"(addr));
}
__device__ __forceinline__ void ldsm4t(uint32_t* r, uint32_t addr) {
    asm volatile("ldmatrix.sync.aligned.m8n8.x4.trans.shared.b16 {%0,%1,%2,%3}, [%4];"
                 : "=r"(r[0]), "=r"(r[1]), "=r"(r[2]), "=r"(r[3]) : "r"(addr));
}
#define CP_ASYNC16(dst, src) \
    asm volatile("cp.async.cg.shared.global [%0], [%1], 16;" :: "r"(dst), "l"(src))
#define CP_COMMIT() asm volatile("cp.async.commit_group;" ::: "memory")
#define CP_WAIT1() asm volatile("cp.async.wait_group 1;" ::: "memory")
#define CP_WAIT0() asm volatile("cp.async.wait_group 0;" ::: "memory")

// ---------------- prep: x fp32 -> bf16 ----------------
__global__ void prep_x(const float* __restrict__ x) {
    int i = blockIdx.x * blockDim.x + threadIdx.x;
    g_xbf[i] = __float2bfloat16(x[i]);
}

// ---------------- prep: all weights fp32 -> bf16 (one pass) ----------------
// layout: [0,200): Wq heads | [200,400): Wk | [400,600): Wv | [600,620): Wl | [620]: fw
__global__ void prep_w(const float* __restrict__ Wq, const float* __restrict__ Wk,
                       const float* __restrict__ Wv, const float* __restrict__ Wl,
                       const float* __restrict__ fw) {
    size_t i = (size_t)blockIdx.x * blockDim.x + threadIdx.x;
    float v;
    if (i < (size_t)200 * WSZ)        v = Wq[i];
    else if (i < (size_t)400 * WSZ)   v = Wk[i - (size_t)200 * WSZ];
    else if (i < (size_t)600 * WSZ)   v = Wv[i - (size_t)400 * WSZ];
    else if (i < (size_t)620 * WSZ)   v = Wl[i - (size_t)600 * WSZ];
    else                              v = fw[i - (size_t)620 * WSZ];
    g_Wb[i] = __float2bfloat16(v);
}

// ---------------- unified bf16 tensor GEMM ----------------
// C[n][j] (j=0..255) = act( A[n][:] . B(j,:) + bias[j] )
// transB=1: B row-major [j][k] (nn.Linear W). transB=0: B row-major [k][j] (x @ W).
// mode 0: relu(t+b) -> bf16 ; mode 1: sigmoid(t)+b -> f32 ; mode 2: t+b -> bf16
// grid (N_TOK/128, 1, nz); block 256. SMEM: As[128][264], Bs[256][264].
constexpr int GEMM_SMEM = 67584 + 135168;   // 202752

__global__ __launch_bounds__(256, 1) void gemm_bf16(
    const __nv_bfloat16* __restrict__ A, const __nv_bfloat16* __restrict__ Bg,
    const float* __restrict__ bias, void* __restrict__ Cv,
    long long c_zstride, int bias_zstride, int transB, int mode) {
    extern __shared__ char sm[];
    __nv_bfloat16* As = (__nv_bfloat16*)sm;             // [128][264]
    __nv_bfloat16* Bs = (__nv_bfloat16*)(sm + 67584);   // [256][264]
    __shared__ float bias_s[256];
    const uint32_t sb = smem_to_u32(sm);

    const int tid = threadIdx.x, wid = tid >> 5, lane = tid & 31;
    const int z = blockIdx.z;
    const int n0 = blockIdx.x * 128;
    const __nv_bfloat16* Bm = Bg + (size_t)z * WSZ;
    const float* biasm = bias + (size_t)z * bias_zstride;

    if (tid < 256) bias_s[tid] = biasm[tid];
    for (int t = tid; t < 4096; t += 256) {               // A tile 128x256
        int r = t >> 5, c = (t & 31) << 3;
        *(uint4*)&As[r * 264 + c] = *(const uint4*)&A[(size_t)(n0 + r) * DIM + c];
    }
    for (int t = tid; t < 8192; t += 256) {               // B full 256x256
        int r = t >> 5, c = (t & 31) << 3;
        *(uint4*)&Bs[r * 264 + c] = *(const uint4*)&Bm[(size_t)r * DIM + c];
    }
    __syncthreads();

    const int wr = (wid & 3) * 32;     // m offset
    const int wc = (wid >> 2) * 128;   // n offset
    float c[2][16][4];
#pragma unroll
    for (int i = 0; i < 2; i++)
#pragma unroll
        for (int j = 0; j < 16; j++)
#pragma unroll
            for (int k = 0; k < 4; k++) c[i][j][k] = 0.f;

    const uint32_t a_base = sb + (uint32_t)(wr + (lane & 15)) * 528 + ((lane >> 4) << 4);
    const uint32_t bK_base = sb + 67584 +
        (uint32_t)(wc + (lane & 7) + ((lane >> 4) << 3)) * 528 + (((lane >> 3) & 1) << 4);
    const uint32_t bT_base = sb + 67584 +
        (uint32_t)((lane & 7) + (((lane >> 3) & 1) << 3)) * 528 + wc * 2 + ((lane >> 4) << 4);

#pragma unroll
    for (int kk = 0; kk < 16; kk++) {
        uint32_t a0[4], a1[4];
        ldsm4(a0, a_base + kk * 32);
        ldsm4(a1, a_base + 16 * 528 + kk * 32);
#pragma unroll
        for (int nq = 0; nq < 8; nq++) {
            uint32_t b[4];
            if (transB) ldsm4(b, bK_base + nq * (16 * 528) + kk * 32);
            else        ldsm4t(b, bT_base + kk * (16 * 528) + nq * 32);
            mma16816(c[0][nq * 2],     a0, b[0], b[1]);
            mma16816(c[0][nq * 2 + 1], a0, b[2], b[3]);
            mma16816(c[1][nq * 2],     a1, b[0], b[1]);
            mma16816(c[1][nq * 2 + 1], a1, b[2], b[3]);
        }
    }

    // epilogue: direct global store
    const int q2 = (lane & 3) * 2;
#pragma unroll
    for (int mi = 0; mi < 2; mi++) {
        int row = n0 + wr + mi * 16 + (lane >> 2);
#pragma unroll
        for (int nf = 0; nf < 16; nf++) {
            int col = wc + nf * 8 + q2;
            float b0 = bias_s[col], b1 = bias_s[col + 1];
            float t0 = c[mi][nf][0], t1 = c[mi][nf][1];
            float t2 = c[mi][nf][2], t3 = c[mi][nf][3];
            if (mode == 0) {
                t0 = fmaxf(t0 + b0, 0.f); t1 = fmaxf(t1 + b1, 0.f);
                t2 = fmaxf(t2 + b0, 0.f); t3 = fmaxf(t3 + b1, 0.f);
            } else if (mode == 2) {
                t0 += b0; t1 += b1; t2 += b0; t3 += b1;
            } else {
                t0 = 1.f / (1.f + expf(-t0)) + b0; t1 = 1.f / (1.f + expf(-t1)) + b1;
                t2 = 1.f / (1.f + expf(-t2)) + b0; t3 = 1.f / (1.f + expf(-t3)) + b1;
            }
            if (mode == 1) {
                float* C = (float*)Cv + (size_t)z * c_zstride;
                *(float2*)&C[(size_t)row * DIM + col]       = make_float2(t0, t1);
                *(float2*)&C[(size_t)(row + 8) * DIM + col] = make_float2(t2, t3);
            } else {
                __nv_bfloat16* C = (__nv_bfloat16*)Cv + (size_t)z * c_zstride;
                *(__nv_bfloat162*)&C[(size_t)row * DIM + col]       = __floats2bfloat162_rn(t0, t1);
                *(__nv_bfloat162*)&C[(size_t)(row + 8) * DIM + col] = __floats2bfloat162_rn(t2, t3);
            }
        }
    }
}

// ================= FA2-style fused flash attention (mma.sync bf16) =================
// BM=128 q rows/CTA, 8 warps x 16 rows, BN=64 keys/tile, full d=256 in regs.
// S lives in C-fragments; softmax in regs; C-frag == A-frag layout => direct PV.
constexpr int Q_OFF = 0;        // bf16 [128][264]
constexpr int K_OFF = 67584;    // 2 stages x bf16 [64][264]
constexpr int V_OFF = 135168;   // 2 stages x bf16 [64][264]
constexpr int KV_STAGE = 33792;
constexpr int ATTN_SMEM = 202752;

__global__ __launch_bounds__(256, 1) void attn_kernel() {
    extern __shared__ char sm[];
    const uint32_t sbase = smem_to_u32(sm);
    const int tid = threadIdx.x, wid = tid >> 5, lane = tid & 31;
    const int head = blockIdx.y;
    const int q0 = blockIdx.x * 128;
    const __nv_bfloat16* Qg = g_QKV + (size_t)(head * 3 + 0) * ND + (size_t)q0 * DIM;
    const __nv_bfloat16* Kg = g_QKV + (size_t)(head * 3 + 1) * ND;
    const __nv_bfloat16* Vg = g_QKV + (size_t)(head * 3 + 2) * ND;

    // Q -> smem (row-major, stride 264 halves)
    for (int t = tid; t < 4096; t += 256) {
        int r = t >> 5, c = (t & 31) << 3;
        *(uint4*)(sm + Q_OFF + (r * 264 + c) * 2) = *(const uint4*)&Qg[(size_t)r * DIM + c];
    }

    auto issueKV = [&](int kt, int stage) {
        const char* Ks = (const char*)(Kg + (size_t)kt * 64 * DIM);
        const char* Vs = (const char*)(Vg + (size_t)kt * 64 * DIM);
        uint32_t kd = sbase + K_OFF + stage * KV_STAGE;
        uint32_t vd = sbase + V_OFF + stage * KV_STAGE;
#pragma unroll
        for (int i = 0; i < 8; i++) {
            int t = tid + i * 256;
            int row = t >> 5, c = t & 31;
            uint32_t doff = row * 528 + c * 16;
            CP_ASYNC16(kd + doff, Ks + row * 512 + c * 16);
            CP_ASYNC16(vd + doff, Vs + row * 512 + c * 16);
        }
    };
    issueKV(0, 0); CP_COMMIT();
    issueKV(1, 1); CP_COMMIT();

    const int r0 = wid * 16;
    const uint32_t qa = sbase + Q_OFF + (uint32_t)(r0 + (lane & 15)) * 528 + ((lane >> 4) << 4);
    const uint32_t ka = (uint32_t)((lane & 7) + ((lane >> 4) << 3)) * 528 + (((lane >> 3) & 1) << 4);
    const uint32_t va = (uint32_t)((lane & 7) + (((lane >> 3) & 1) << 3)) * 528 + ((lane >> 4) << 4);

    float o[128];
#pragma unroll
    for (int i = 0; i < 128; i++) o[i] = 0.f;
    float rsum0 = 0.f, rsum1 = 0.f;

    for (int kt = 0; kt < 64; kt++) {
        if (kt < 63) { CP_WAIT1(); } else { CP_WAIT0(); }
        __syncthreads();
        const uint32_t Kst = sbase + K_OFF + (kt & 1) * KV_STAGE;
        const uint32_t Vst = sbase + V_OFF + (kt & 1) * KV_STAGE;

        // ---- S = Q @ K^T (16x64 per warp, K=256) ----
        float s[32];
#pragma unroll
        for (int i = 0; i < 32; i++) s[i] = 0.f;
#pragma unroll
        for (int kk = 0; kk < 16; kk++) {
            uint32_t a[4];
            ldsm4(a, qa + kk * 32);
#pragma unroll
            for (int np = 0; np < 4; np++) {
                uint32_t b[4];
                ldsm4(b, Kst + ka + np * 8448 + kk * 32);
                mma16816(&s[np * 8], a, b[0], b[1]);
                mma16816(&s[np * 8 + 4], a, b[2], b[3]);
            }
        }
        // ---- p = e^{0.5*tanh(s/32)} (1 MUFU + FMA poly); partial rowsums ----
#pragma unroll
        for (int n = 0; n < 8; n++) {
            float p0 = softp(s[n * 4 + 0]);
            float p1 = softp(s[n * 4 + 1]);
            float p2 = softp(s[n * 4 + 2]);
            float p3 = softp(s[n * 4 + 3]);
            rsum0 += p0 + p1; rsum1 += p2 + p3;
            s[n * 4 + 0] = p0; s[n * 4 + 1] = p1; s[n * 4 + 2] = p2; s[n * 4 + 3] = p3;
        }
        // ---- pack P into A-fragments (C-frag layout == A-frag layout) ----
        uint32_t pk[16];
#pragma unroll
        for (int kk = 0; kk < 4; kk++) {
            pk[kk * 4 + 0] = __float_as_uint(0.f);  // placeholder, overwritten below
        }
#pragma unroll
        for (int kk = 0; kk < 4; kk++) {
            __nv_bfloat162 h0 = __floats2bfloat162_rn(s[kk * 8 + 0], s[kk * 8 + 1]);
            __nv_bfloat162 h1 = __floats2bfloat162_rn(s[kk * 8 + 2], s[kk * 8 + 3]);
            __nv_bfloat162 h2 = __floats2bfloat162_rn(s[kk * 8 + 4], s[kk * 8 + 5]);
            __nv_bfloat162 h3 = __floats2bfloat162_rn(s[kk * 8 + 6], s[kk * 8 + 7]);
            pk[kk * 4 + 0] = *(uint32_t*)&h0;
            pk[kk * 4 + 1] = *(uint32_t*)&h1;
            pk[kk * 4 + 2] = *(uint32_t*)&h2;
            pk[kk * 4 + 3] = *(uint32_t*)&h3;
        }
        // ---- O += P @ V (16x256 per warp, k=64) ----
#pragma unroll
        for (int kk = 0; kk < 4; kk++) {
#pragma unroll
            for (int np = 0; np < 16; np++) {
                uint32_t b[4];
                ldsm4t(b, Vst + va + kk * 8448 + np * 32);
                mma16816(&o[np * 8], &pk[kk * 4], b[0], b[1]);
                mma16816(&o[np * 8 + 4], &pk[kk * 4], b[2], b[3]);
            }
        }
        if (kt < 62) {
            __syncthreads();
            issueKV(kt + 2, kt & 1);
            CP_COMMIT();
        }
    }

    // ---- finalize: complete row sums across the quad, normalize, store bf16 ----
    rsum0 += __shfl_xor_sync(0xffffffffu, rsum0, 1);
    rsum0 += __shfl_xor_sync(0xffffffffu, rsum0, 2);
    rsum1 += __shfl_xor_sync(0xffffffffu, rsum1, 1);
    rsum1 += __shfl_xor_sync(0xffffffffu, rsum1, 2);
    float inv0 = 1.0f / rsum0, inv1 = 1.0f / rsum1;

    const int row = q0 + r0 + (lane >> 2);
    const int colb = (lane & 3) * 2;
    __nv_bfloat16* O0 = g_O + (size_t)head * ND + (size_t)row * DIM;
    __nv_bfloat16* O1 = O0 + 8 * DIM;
#pragma unroll
    for (int n = 0; n < 32; n++) {
        *(__nv_bfloat162*)&O0[n * 8 + colb] =
            __floats2bfloat162_rn(o[n * 4 + 0] * inv0, o[n * 4 + 1] * inv0);
        *(__nv_bfloat162*)&O1[n * 8 + colb] =
            __floats2bfloat162_rn(o[n * 4 + 2] * inv1, o[n * 4 + 3] * inv1);
    }
}

// ---------------- mean over heads (deterministic, no atomics) -> bf16 ----------------
__global__ void reduce_kernel(__nv_bfloat16* __restrict__ out) {
    int i = blockIdx.x * blockDim.x + threadIdx.x;
    const __nv_bfloat16* p = g_O + i;
    float s = 0.f;
#pragma unroll 8
    for (int h = 0; h < NUM_HEADS; h++) s += __bfloat162float(p[(size_t)h * ND]);
    out[i] = __float2bfloat16(s * (1.0f / NUM_HEADS));
}

// ---------------- launch ----------------
extern "C" void kernel_launch(void* const* d_in, const int* in_sizes, int n_in,
                              void* d_out, int out_size) {
    const float* x  = (const float*)d_in[0];
    const float* Wq = (const float*)d_in[1];
    const float* bq = (const float*)d_in[2];
    const float* Wk = (const float*)d_in[3];
    const float* bk = (const float*)d_in[4];
    const float* Wv = (const float*)d_in[5];
    const float* bv = (const float*)d_in[6];
    const float* Wl = (const float*)d_in[7];
    const float* bl = (const float*)d_in[8];
    const float* fw = (const float*)d_in[9];
    const float* fb = (const float*)d_in[10];

    cudaFuncSetAttribute(gemm_bf16, cudaFuncAttributeMaxDynamicSharedMemorySize, GEMM_SMEM);
    cudaFuncSetAttribute(attn_kernel, cudaFuncAttributeMaxDynamicSharedMemorySize, ATTN_SMEM);

    __nv_bfloat16* xbf = nullptr;  cudaGetSymbolAddress((void**)&xbf, g_xbf);
    __nv_bfloat16* wb = nullptr;   cudaGetSymbolAddress((void**)&wb, g_Wb);
    __nv_bfloat16* qkv = nullptr;  cudaGetSymbolAddress((void**)&qkv, g_QKV);
    __nv_bfloat16* hb = nullptr;   cudaGetSymbolAddress((void**)&hb, g_hb);

    const size_t nW = (size_t)(3 * NUM_HEADS + NUM_LAYERS + 1) * WSZ;

    // launches #0,#1
    prep_x<<<ND / 256, 256>>>(x);
    prep_w<<<(int)(nW / 256), 256>>>(Wq, Wk, Wv, Wl, fw);

    // launches #2,#3,#4: Q/K/V projections (mode 2 = +bias, bf16 out)
    gemm_bf16<<<dim3(N_TOK / 128, 1, NUM_HEADS), 256, GEMM_SMEM>>>(
        xbf, wb + (size_t)0 * NUM_HEADS * WSZ, bq, qkv + (size_t)0 * ND,
        (long long)3 * ND, DIM, 1, 2);
    gemm_bf16<<<dim3(N_TOK / 128, 1, NUM_HEADS), 256, GEMM_SMEM>>>(
        xbf, wb + (size_t)1 * NUM_HEADS * WSZ, bk, qkv + (size_t)1 * ND,
        (long long)3 * ND, DIM, 1, 2);
    gemm_bf16<<<dim3(N_TOK / 128, 1, NUM_HEADS), 256, GEMM_SMEM>>>(
        xbf, wb + (size_t)2 * NUM_HEADS * WSZ, bv, qkv + (size_t)2 * ND,
        (long long)3 * ND, DIM, 1, 2);

    // launch #5 (ncu -s 5 -c 1 captures this one)
    attn_kernel<<<dim3(N_TOK / 128, NUM_HEADS), 256, ATTN_SMEM>>>();

    reduce_kernel<<<ND / 256, 256>>>(hb);

    for (int l = 0; l < NUM_LAYERS; l++) {
        gemm_bf16<<<dim3(N_TOK / 128, 1, 1), 256, GEMM_SMEM>>>(
            hb + (size_t)(l & 1) * ND, wb + (size_t)(600 + l) * WSZ, bl + (size_t)l * DIM,
            hb + (size_t)((l + 1) & 1) * ND, 0, 0, 1, 0);
    }
    gemm_bf16<<<dim3(N_TOK / 128, 1, 1), 256, GEMM_SMEM>>>(
        hb, wb + (size_t)620 * WSZ, fb, d_out, 0, 0, 0, 1);
}